// round 6
// baseline (speedup 1.0000x reference)
#include <cuda_runtime.h>
#include <math.h>

#define YPB      64                  // years per block -> 128 blocks on 8192 yrs
#define W_YEARS  6                   // warmup years
#define SLOTS    (YPB + W_YEARS)     // 70 year-slots incl. halo

#define PI_F 3.14159265358979323846f

__device__ __forceinline__ float fast_lg2(float x) {
    float r; asm("lg2.approx.f32 %0, %1;" : "=f"(r) : "f"(x)); return r;
}
__device__ __forceinline__ float fast_ex2(float x) {
    float r; asm("ex2.approx.f32 %0, %1;" : "=f"(r) : "f"(x)); return r;
}
__device__ __forceinline__ float fast_pow(float x, float e) {
    return fast_ex2(e * fast_lg2(x));
}

// ---------------- device state (no allocation) ----------------
__device__ float        g_width[8192];
__device__ unsigned int g_ticket = 0;

__device__ __constant__ float c_NDAYS[13] = {0,31,28,31,30,31,30,31,31,30,31,30,31};
__device__ __constant__ int   c_CDAYS[13] = {0,31,59,90,120,151,181,212,243,273,304,334,365};

__global__ void __launch_bounds__(YPB, 1)
vsl_fused_kernel(const int* __restrict__ phi_ptr,
                 const float* __restrict__ T, const float* __restrict__ P,
                 const float* __restrict__ pT1, const float* __restrict__ pT2,
                 const float* __restrict__ pM1, const float* __restrict__ pM2,
                 float* __restrict__ out, int nyrs) {
    __shared__ float sh_dtsi[365];
    __shared__ float sh_invmax;
    __shared__ float sh_L[12];
    __shared__ float sh_gE[12];
    __shared__ float sh_A [12 * SLOTS];   // month-major: [m][slot] -> conflict-free LDS
    __shared__ float sh_B [12 * SLOTS];
    __shared__ float sh_gT[12 * SLOTS];
    __shared__ float sh_red[2];
    __shared__ float sh_bcast;
    __shared__ unsigned int sh_last;

    const int tid     = threadIdx.x;
    const int blockY0 = blockIdx.x * YPB;
    const float latr  = (float)(*phi_ptr) * (PI_F / 180.0f);
    const float T1 = *pT1, T2 = *pT2, M1 = *pM1, M2 = *pM2;
    const float invDT = 1.0f / (T2 - T1);
    const float invDM = 1.0f / (M2 - M1);

    // ---- stage 1: daily insolation (redundant per block) ----
    const float tlat = __tanf(latr);
    const float slat = __sinf(latr);
    const float clat = __cosf(latr);
    for (int j = tid; j < 365; j += YPB) {
        float jday = (float)(j + 1);
        float sd = asinf(0.39874907f * __sinf(PI_F * (jday - 80.0f) * (1.0f / 180.0f)));
        float y  = fminf(fmaxf(-tlat * __tanf(sd), -1.0f), 1.0f);
        float hdl = acosf(y);
        sh_dtsi[j] = hdl * slat * __sinf(sd) + clat * __cosf(sd) * __sinf(hdl);
    }
    __syncthreads();

    if (tid < 32) {
        float mx = -1.0f;
        for (int i = tid; i < 365; i += 32) mx = fmaxf(mx, sh_dtsi[i]);
        #pragma unroll
        for (int o = 16; o > 0; o >>= 1)
            mx = fmaxf(mx, __shfl_xor_sync(0xFFFFFFFF, mx, o));
        if (tid == 0) sh_invmax = 1.0f / mx;
    }
    __syncthreads();

    if (tid < 12) {
        const int c0 = c_CDAYS[tid];
        const int c1 = c_CDAYS[tid + 1];
        float s = 0.0f;
        for (int i = c0; i < c1; i++) s += sh_dtsi[i];
        sh_gE[tid] = s * sh_invmax / (float)(c1 - c0);

        float jday_mid = (float)c0 + 0.5f * c_NDAYS[tid + 1];
        float m_star = 1.0f - tlat * __tanf(0.40908772f * __cosf(jday_mid * (PI_F / 182.625f)));
        m_star = fminf(fmaxf(m_star, 0.0f), 2.0f);
        float nhrs = 24.0f * acosf(1.0f - m_star) * (1.0f / PI_F);
        sh_L[tid] = c_NDAYS[tid + 1] * (1.0f / 30.0f) * (nhrs * (1.0f / 12.0f));
    }
    __syncthreads();

    // ---- stage 2: PET -> (A, B, gT), month-major shared ----
    // M' = clamp(A*M + B - B*(M/0.76)^4.886),  A = 0.907 - ep*(0.001/0.76), B = p/1000
    for (int s = tid; s < SLOTS; s += YPB) {
        const int yy = blockY0 - W_YEARS + s;
        if (yy < 0 || yy >= nyrs) {
            #pragma unroll
            for (int m = 0; m < 12; m++) {
                sh_A [m*SLOTS + s] = 1.0f;   // identity step (exact for y < W)
                sh_B [m*SLOTS + s] = 0.0f;
                sh_gT[m*SLOTS + s] = 0.0f;
            }
        } else {
            float t[12];
            #pragma unroll
            for (int m = 0; m < 12; m++) t[m] = T[yy*12 + m];

            float I = 0.0f;
            #pragma unroll
            for (int m = 0; m < 12; m++) {
                float is = t[m] * 0.2f;
                if (is > 0.0f) I += fast_pow(is, 1.514f);
            }
            const float a = ((6.75e-7f * I - 7.71e-5f) * I + 0.0179f) * I + 0.49f;
            const float invI = 1.0f / I;

            #pragma unroll
            for (int m = 0; m < 12; m++) {
                float Tm = t[m];
                float ep;
                if (Tm < 0.0f)        ep = 0.0f;
                else if (Tm < 26.5f)  ep = 16.0f * sh_L[m] * fast_pow(10.0f * Tm * invI, a);
                else                  ep = -415.85f + 32.25f * Tm - 0.43f * Tm * Tm;
                sh_A [m*SLOTS + s] = 0.907f - ep * 1.31578947e-3f;
                sh_B [m*SLOTS + s] = P[yy*12 + m] * 0.001f;
                sh_gT[m*SLOTS + s] = fminf(fmaxf((Tm - T1) * invDT, 0.0f), 1.0f);
            }
        }
    }
    __syncthreads();

    // ---- stage 3: warm-started chain + growth response ----
    const int y = blockY0 + tid;
    if (y < nyrs) {
        const float PEXP = 4.886f;
        const float POFF = 1.9345078f;        // 4.886 * log2(1/0.76)
        const float M1s  = M1 * invDM;

        float M = 0.2f;

        #pragma unroll
        for (int j = 0; j < W_YEARS; j++) {
            const int s = tid + j;
            #pragma unroll
            for (int m = 0; m < 12; m++) {
                float A  = sh_A[m*SLOTS + s];
                float B  = sh_B[m*SLOTS + s];
                float pw = fast_ex2(fmaf(PEXP, fast_lg2(M), POFF));
                float t  = fmaf(A, M, B);
                M = fminf(fmaxf(fmaf(-B, pw, t), 0.01f), 0.76f);
            }
        }

        float w = 0.0f;
        {
            const int s = tid + W_YEARS;
            #pragma unroll
            for (int m = 0; m < 12; m++) {
                float A  = sh_A[m*SLOTS + s];
                float B  = sh_B[m*SLOTS + s];
                float pw = fast_ex2(fmaf(PEXP, fast_lg2(M), POFF));
                float t  = fmaf(A, M, B);
                M = fminf(fmaxf(fmaf(-B, pw, t), 0.01f), 0.76f);

                float gM = fminf(fmaxf(fmaf(M, invDM, -M1s), 0.0f), 1.0f);
                float gT = sh_gT[m*SLOTS + s];
                w = fmaf(fminf(gT, gM), sh_gE[m], w);
            }
        }
        g_width[y] = w;
    }

    // ---- stage 4: last-arriving block standardizes ----
    __threadfence();
    __syncthreads();
    if (tid == 0) sh_last = (atomicAdd(&g_ticket, 1u) == gridDim.x - 1u);
    __syncthreads();
    if (!sh_last) return;

    const int lane = tid & 31;
    const int wid  = tid >> 5;

    // pass 1: mean (loop-based, L2-resident)
    float s = 0.0f;
    for (int i = tid; i < nyrs; i += YPB) s += __ldcg(&g_width[i]);
    #pragma unroll
    for (int o = 16; o > 0; o >>= 1) s += __shfl_xor_sync(0xFFFFFFFF, s, o);
    if (lane == 0) sh_red[wid] = s;
    __syncthreads();
    const float mean = (sh_red[0] + sh_red[1]) / (float)nyrs;
    __syncthreads();

    // pass 2: variance (unbiased)
    float ss = 0.0f;
    for (int i = tid; i < nyrs; i += YPB) {
        float d = __ldcg(&g_width[i]) - mean;
        ss = fmaf(d, d, ss);
    }
    #pragma unroll
    for (int o = 16; o > 0; o >>= 1) ss += __shfl_xor_sync(0xFFFFFFFF, ss, o);
    if (lane == 0) sh_red[wid] = ss;
    __syncthreads();
    const float inv = rsqrtf((sh_red[0] + sh_red[1]) / (float)(nyrs - 1));

    // pass 3: write standardized output
    for (int i = tid; i < nyrs; i += YPB)
        out[i] = (__ldcg(&g_width[i]) - mean) * inv;

    if (tid == 0) g_ticket = 0;   // reset for next graph replay
}

// ---------------- launch ----------------
extern "C" void kernel_launch(void* const* d_in, const int* in_sizes, int n_in,
                              void* d_out, int out_size) {
    const int*   phi = (const int*)d_in[2];
    const float* T   = (const float*)d_in[3];
    const float* P   = (const float*)d_in[4];
    const float* T1  = (const float*)d_in[5];
    const float* T2  = (const float*)d_in[6];
    const float* M1  = (const float*)d_in[7];
    const float* M2  = (const float*)d_in[8];
    float* out = (float*)d_out;

    const int nyrs = in_sizes[3] / 12;
    const int nblk = (nyrs + YPB - 1) / YPB;

    vsl_fused_kernel<<<nblk, YPB>>>(phi, T, P, T1, T2, M1, M2, out, nyrs);
}

// round 7
// speedup vs baseline: 2.1912x; 2.1912x over previous
#include <cuda_runtime.h>
#include <math.h>

#define NYRS_MAX 8192
#define YPB      256                 // years per block -> 32 blocks, 8 warps/SM
#define W_YEARS  6                   // warmup years: 3 crude + 3 accurate
#define W_CRUDE  3
#define SLOTS    (YPB + W_YEARS)     // 262 year-slots incl. halo

#define PI_F 3.14159265358979323846f

__device__ __forceinline__ float fast_lg2(float x) {
    float r; asm("lg2.approx.f32 %0, %1;" : "=f"(r) : "f"(x)); return r;
}
__device__ __forceinline__ float fast_ex2(float x) {
    float r; asm("ex2.approx.f32 %0, %1;" : "=f"(r) : "f"(x)); return r;
}
__device__ __forceinline__ float fast_pow(float x, float e) {
    return fast_ex2(e * fast_lg2(x));
}
// deg-9 odd asin, |x| <= ~0.45 (err < 4e-6)
__device__ __forceinline__ float asin_poly(float x) {
    float x2 = x * x;
    float p = fmaf(x2, 0.030381944f, 0.044642857f);
    p = fmaf(x2, p, 0.075f);
    p = fmaf(x2, p, 0.16666667f);
    return fmaf(x * x2, p, x);
}
__device__ __forceinline__ float fast_acos(float x) {
    return (fabsf(x) <= 0.45f) ? (PI_F * 0.5f - asin_poly(x)) : acosf(x);
}

// ---------------- device state (no allocation) ----------------
__device__ float        g_width[NYRS_MAX];
__device__ unsigned int g_ticket = 0;

__device__ __constant__ float c_NDAYS[13] = {0,31,28,31,30,31,30,31,31,30,31,30,31};
__device__ __constant__ int   c_CDAYS[13] = {0,31,59,90,120,151,181,212,243,273,304,334,365};

__global__ void __launch_bounds__(YPB, 1)
vsl_fused_kernel(const int* __restrict__ phi_ptr,
                 const float* __restrict__ T, const float* __restrict__ P,
                 const float* __restrict__ pT1, const float* __restrict__ pT2,
                 const float* __restrict__ pM1, const float* __restrict__ pM2,
                 float* __restrict__ out, int nyrs) {
    __shared__ float sh_dtsi[365];
    __shared__ float sh_invmax;
    __shared__ float sh_L[12];
    __shared__ float sh_gE[12];
    __shared__ float sh_A [12 * SLOTS];   // month-major -> conflict-free LDS
    __shared__ float sh_B [12 * SLOTS];
    __shared__ float sh_gT[12 * SLOTS];
    __shared__ float sh_red[8];
    __shared__ float sh_bcast;
    __shared__ unsigned int sh_last;

    const int tid     = threadIdx.x;
    const int blockY0 = blockIdx.x * YPB;
    const float latr  = (float)(*phi_ptr) * (PI_F / 180.0f);
    const float T1 = *pT1, T2 = *pT2, M1 = *pM1, M2 = *pM2;
    const float invDT = 1.0f / (T2 - T1);
    const float invDM = 1.0f / (M2 - M1);

    // ---- stage 1: daily insolation, transcendental-minimized ----
    // sd = asin(k sin x) => sin(sd) = k sin x, cos(sd) = sqrt(1 - sin^2).
    // hdl = acos(y) => sin(hdl) = sqrt(1-y^2) (exact incl. clip at +-1).
    const float tlat = __tanf(latr);
    const float slat = __sinf(latr);
    const float clat = __cosf(latr);
    for (int j = tid; j < 365; j += YPB) {
        float jday = (float)(j + 1);
        float ssd  = 0.39874907f * __sinf(PI_F * (jday - 80.0f) * (1.0f / 180.0f));
        float csd  = sqrtf(1.0f - ssd * ssd);
        float y    = fminf(fmaxf(-tlat * ssd * (1.0f / csd), -1.0f), 1.0f);
        float hdl  = fast_acos(y);
        float shdl = sqrtf(fmaxf(1.0f - y * y, 0.0f));
        sh_dtsi[j] = hdl * slat * ssd + clat * csd * shdl;
    }
    __syncthreads();

    if (tid < 32) {
        float mx = -1.0f;
        for (int i = tid; i < 365; i += 32) mx = fmaxf(mx, sh_dtsi[i]);
        #pragma unroll
        for (int o = 16; o > 0; o >>= 1)
            mx = fmaxf(mx, __shfl_xor_sync(0xFFFFFFFF, mx, o));
        if (tid == 0) sh_invmax = 1.0f / mx;
    }
    __syncthreads();

    if (tid < 12) {
        const int c0 = c_CDAYS[tid];
        const int c1 = c_CDAYS[tid + 1];
        float s = 0.0f;
        for (int i = c0; i < c1; i++) s += sh_dtsi[i];
        sh_gE[tid] = s * sh_invmax / (float)(c1 - c0);

        float jday_mid = (float)c0 + 0.5f * c_NDAYS[tid + 1];
        float m_star = 1.0f - tlat * __tanf(0.40908772f * __cosf(jday_mid * (PI_F / 182.625f)));
        m_star = fminf(fmaxf(m_star, 0.0f), 2.0f);
        float nhrs = 24.0f * fast_acos(1.0f - m_star) * (1.0f / PI_F);
        sh_L[tid] = c_NDAYS[tid + 1] * (1.0f / 30.0f) * (nhrs * (1.0f / 12.0f));
    }
    __syncthreads();

    // ---- stage 2: PET -> (A, B, gT), month-major shared ----
    // M' = clamp(A*M + B - B*(M/0.76)^4.886), A = 0.907 - ep*(0.001/0.76), B = p/1000
    for (int s = tid; s < SLOTS; s += YPB) {
        const int yy = blockY0 - W_YEARS + s;
        if (yy < 0 || yy >= nyrs) {
            #pragma unroll
            for (int m = 0; m < 12; m++) {
                sh_A [m*SLOTS + s] = 1.0f;   // identity step (B=0 -> M unchanged, exact)
                sh_B [m*SLOTS + s] = 0.0f;
                sh_gT[m*SLOTS + s] = 0.0f;
            }
        } else {
            float t[12];
            #pragma unroll
            for (int m = 0; m < 12; m++) t[m] = T[yy*12 + m];

            float I = 0.0f;
            #pragma unroll
            for (int m = 0; m < 12; m++) {
                float is = t[m] * 0.2f;
                if (is > 0.0f) I += fast_pow(is, 1.514f);
            }
            const float a = ((6.75e-7f * I - 7.71e-5f) * I + 0.0179f) * I + 0.49f;
            const float invI = 1.0f / I;

            #pragma unroll
            for (int m = 0; m < 12; m++) {
                float Tm = t[m];
                float ep;
                if (Tm < 0.0f)        ep = 0.0f;
                else if (Tm < 26.5f)  ep = 16.0f * sh_L[m] * fast_pow(10.0f * Tm * invI, a);
                else                  ep = -415.85f + 32.25f * Tm - 0.43f * Tm * Tm;
                sh_A [m*SLOTS + s] = 0.907f - ep * 1.31578947e-3f;
                sh_B [m*SLOTS + s] = P[yy*12 + m] * 0.001f;
                sh_gT[m*SLOTS + s] = fminf(fmaxf((Tm - T1) * invDT, 0.0f), 1.0f);
            }
        }
    }
    __syncthreads();

    // ---- stage 3: warm-started chain + growth response ----
    const int y = blockY0 + tid;
    if (y < nyrs) {
        const float PEXP = 4.886f;
        const float POFF = 1.9345078f;        // 4.886 * log2(1/0.76)
        const float invMMAX = 1.0f / 0.76f;
        const float M1s  = M1 * invDM;

        float M = 0.2f;

        // crude warmup: pw ~= r^5 (1 + 0.114(1-r)); err <= 1.1e-3, decays
        // by 0.84^36 over the accurate warmup -> ~1e-6 residual.
        #pragma unroll
        for (int j = 0; j < W_CRUDE; j++) {
            const int s = tid + j;
            #pragma unroll
            for (int m = 0; m < 12; m++) {
                float A  = sh_A[m*SLOTS + s];
                float B  = sh_B[m*SLOTS + s];
                float r  = M * invMMAX;
                float r2 = r * r;
                float r5 = r2 * r2 * r;
                float pw = r5 * fmaf(-0.114f, r, 1.114f);
                float t  = fmaf(A, M, B);
                M = fminf(fmaxf(fmaf(-B, pw, t), 0.01f), 0.76f);
            }
        }
        // accurate warmup
        #pragma unroll
        for (int j = W_CRUDE; j < W_YEARS; j++) {
            const int s = tid + j;
            #pragma unroll
            for (int m = 0; m < 12; m++) {
                float A  = sh_A[m*SLOTS + s];
                float B  = sh_B[m*SLOTS + s];
                float pw = fast_ex2(fmaf(PEXP, fast_lg2(M), POFF));
                float t  = fmaf(A, M, B);
                M = fminf(fmaxf(fmaf(-B, pw, t), 0.01f), 0.76f);
            }
        }
        // the real 12 months
        float w = 0.0f;
        {
            const int s = tid + W_YEARS;
            #pragma unroll
            for (int m = 0; m < 12; m++) {
                float A  = sh_A[m*SLOTS + s];
                float B  = sh_B[m*SLOTS + s];
                float pw = fast_ex2(fmaf(PEXP, fast_lg2(M), POFF));
                float t  = fmaf(A, M, B);
                M = fminf(fmaxf(fmaf(-B, pw, t), 0.01f), 0.76f);

                float gM = fminf(fmaxf(fmaf(M, invDM, -M1s), 0.0f), 1.0f);
                w = fmaf(fminf(sh_gT[m*SLOTS + s], gM), sh_gE[m], w);
            }
        }
        g_width[y] = w;
    }

    // ---- stage 4: last-arriving block standardizes ----
    __threadfence();
    __syncthreads();
    if (tid == 0) sh_last = (atomicAdd(&g_ticket, 1u) == gridDim.x - 1u);
    __syncthreads();
    if (!sh_last) return;

    const int lane = tid & 31;
    const int wid  = tid >> 5;
    const int PER  = NYRS_MAX / YPB;   // 32

    float v[PER];
    float s = 0.0f;
    int cnt = 0;
    #pragma unroll
    for (int i = 0; i < PER; i++) {
        int idx = tid + i * YPB;
        v[i] = (idx < nyrs) ? __ldcg(&g_width[idx]) : 0.0f;
        if (idx < nyrs) { s += v[i]; cnt = i + 1; }
    }
    #pragma unroll
    for (int o = 16; o > 0; o >>= 1) s += __shfl_xor_sync(0xFFFFFFFF, s, o);
    if (lane == 0) sh_red[wid] = s;
    __syncthreads();
    if (wid == 0) {
        float t = (lane < 8) ? sh_red[lane] : 0.0f;
        #pragma unroll
        for (int o = 4; o > 0; o >>= 1) t += __shfl_xor_sync(0xFFFFFFFF, t, o);
        if (lane == 0) sh_bcast = t / (float)nyrs;
    }
    __syncthreads();
    const float mean = sh_bcast;
    __syncthreads();

    float ss = 0.0f;
    #pragma unroll
    for (int i = 0; i < PER; i++) {
        if (i < cnt) { float d = v[i] - mean; ss = fmaf(d, d, ss); }
    }
    #pragma unroll
    for (int o = 16; o > 0; o >>= 1) ss += __shfl_xor_sync(0xFFFFFFFF, ss, o);
    if (lane == 0) sh_red[wid] = ss;
    __syncthreads();
    if (wid == 0) {
        float t = (lane < 8) ? sh_red[lane] : 0.0f;
        #pragma unroll
        for (int o = 4; o > 0; o >>= 1) t += __shfl_xor_sync(0xFFFFFFFF, t, o);
        if (lane == 0) sh_bcast = rsqrtf(t / (float)(nyrs - 1));
    }
    __syncthreads();
    const float inv = sh_bcast;

    #pragma unroll
    for (int i = 0; i < PER; i++) {
        int idx = tid + i * YPB;
        if (idx < nyrs) out[idx] = (v[i] - mean) * inv;
    }

    if (tid == 0) g_ticket = 0;   // reset for next graph replay
}

// ---------------- launch ----------------
extern "C" void kernel_launch(void* const* d_in, const int* in_sizes, int n_in,
                              void* d_out, int out_size) {
    const int*   phi = (const int*)d_in[2];
    const float* T   = (const float*)d_in[3];
    const float* P   = (const float*)d_in[4];
    const float* T1  = (const float*)d_in[5];
    const float* T2  = (const float*)d_in[6];
    const float* M1  = (const float*)d_in[7];
    const float* M2  = (const float*)d_in[8];
    float* out = (float*)d_out;

    const int nyrs = in_sizes[3] / 12;
    const int nblk = (nyrs + YPB - 1) / YPB;

    vsl_fused_kernel<<<nblk, YPB>>>(phi, T, P, T1, T2, M1, M2, out, nyrs);
}